// round 6
// baseline (speedup 1.0000x reference)
#include <cuda_runtime.h>
#include <cuda_bf16.h>
#include <math.h>

#define T_TOKENS   8192
#define DIM        1024
#define HIDDEN     2048
#define NEXP       8
#define TOPK       2
#define NROWS      (T_TOKENS * TOPK)   // 16384 (every token picks exactly 2 experts)

#define BM 128
#define BN 128
#define BK 16
#define MAXTILES 136                    // sum ceil(n_e/128) <= 16384/128 + 8

// ---------------- scratch (__device__ globals; no allocations) ----------------
__device__ float g_hidden[(size_t)NROWS * HIDDEN];   // 128 MiB
__device__ float g_ybuf[(size_t)NROWS * DIM];        // 64 MiB
__device__ int   g_counts[NEXP];
__device__ int   g_cursor[NEXP];
__device__ int   g_offsets[NEXP];
__device__ float g_psum[NEXP];
__device__ int   g_topk_idx[T_TOKENS * TOPK];
__device__ float g_topk_gate[T_TOKENS * TOPK];
__device__ int   g_row_token[NROWS];                 // global row -> token
__device__ int   g_token_row[T_TOKENS * TOPK];       // (token,slot) -> global row
__device__ int   g_tile_expert[MAXTILES];
__device__ int   g_tile_row[MAXTILES];
__device__ int   g_tile_m[MAXTILES];
__device__ int   g_ntiles;

// ---------------- init ----------------
__global__ void init_kernel() {
    int i = threadIdx.x;
    if (i < NEXP) {
        g_counts[i] = 0;
        g_cursor[i] = 0;
        g_psum[i]   = 0.f;
    }
}

// ---------------- router: warp per token ----------------
__global__ void router_kernel(const float* __restrict__ x,
                              const float* __restrict__ rw) {
    __shared__ float s_rw[NEXP * DIM];   // 32 KB
    for (int i = threadIdx.x; i < NEXP * DIM; i += 256) s_rw[i] = rw[i];
    __syncthreads();

    int warp = threadIdx.x >> 5;
    int lane = threadIdx.x & 31;
    int t = blockIdx.x * 8 + warp;      // grid 1024 * 8 warps = 8192 tokens

    const float* xr = x + (size_t)t * DIM;
    float acc[NEXP];
#pragma unroll
    for (int e = 0; e < NEXP; e++) acc[e] = 0.f;

    for (int j = lane; j < DIM; j += 32) {
        float xv = xr[j];
#pragma unroll
        for (int e = 0; e < NEXP; e++) acc[e] += xv * s_rw[e * DIM + j];
    }
#pragma unroll
    for (int e = 0; e < NEXP; e++) {
#pragma unroll
        for (int o = 16; o > 0; o >>= 1)
            acc[e] += __shfl_down_sync(0xffffffff, acc[e], o);
    }

    if (lane == 0) {
        // full softmax (for P_i)
        float m = acc[0];
#pragma unroll
        for (int e = 1; e < NEXP; e++) m = fmaxf(m, acc[e]);
        float p[NEXP], s = 0.f;
#pragma unroll
        for (int e = 0; e < NEXP; e++) { p[e] = expf(acc[e] - m); s += p[e]; }
        float inv = 1.f / s;
#pragma unroll
        for (int e = 0; e < NEXP; e++) atomicAdd(&g_psum[e], p[e] * inv);

        // top-2 (lowest index on ties, matching lax.top_k)
        int i1 = 0;
#pragma unroll
        for (int e = 1; e < NEXP; e++) if (acc[e] > acc[i1]) i1 = e;
        int i2 = (i1 == 0) ? 1 : 0;
#pragma unroll
        for (int e = 0; e < NEXP; e++)
            if (e != i1 && acc[e] > acc[i2]) i2 = e;

        float g1 = 1.f / (1.f + expf(acc[i2] - acc[i1]));
        float g2 = 1.f - g1;

        g_topk_idx[t * 2 + 0]  = i1;
        g_topk_idx[t * 2 + 1]  = i2;
        g_topk_gate[t * 2 + 0] = g1;
        g_topk_gate[t * 2 + 1] = g2;
        atomicAdd(&g_counts[i1], 1);
        atomicAdd(&g_counts[i2], 1);
    }
}

// ---------------- schedule: offsets + tile list + aux loss ----------------
__global__ void schedule_kernel(float* __restrict__ d_out, int write_aux) {
    if (threadIdx.x == 0) {
        int off = 0, nt = 0;
        for (int e = 0; e < NEXP; e++) {
            g_offsets[e] = off;
            int n = g_counts[e];
            for (int rs = 0; rs < n; rs += BM) {
                g_tile_expert[nt] = e;
                g_tile_row[nt]    = off + rs;
                g_tile_m[nt]      = min(BM, n - rs);
                nt++;
            }
            off += n;
        }
        g_ntiles = nt;
        if (write_aux) {
            float aux = 0.f;
            for (int e = 0; e < NEXP; e++)
                aux += ((float)g_counts[e] / (float)NROWS) *
                       (g_psum[e] / (float)T_TOKENS);
            d_out[(size_t)T_TOKENS * DIM] = (float)NEXP * aux;
        }
    }
}

// ---------------- scatter tokens into expert-grouped rows ----------------
__global__ void scatter_kernel() {
    int t = blockIdx.x * 256 + threadIdx.x;
    if (t >= T_TOKENS) return;
#pragma unroll
    for (int k = 0; k < TOPK; k++) {
        int e   = g_topk_idx[t * 2 + k];
        int pos = atomicAdd(&g_cursor[e], 1);
        int r   = g_offsets[e] + pos;
        g_row_token[r]         = t;
        g_token_row[t * 2 + k] = r;
    }
}

__device__ __forceinline__ float gelu_exact(float v) {
    return 0.5f * v * (1.f + erff(v * 0.70710678118654752f));
}

// ---------------- grouped GEMM ----------------
// LAYER1: C[r,n] = gelu( sum_k x[row_token[r],k] * w1[e][n,k] + b1[e][n] ) -> g_hidden
// LAYER2: C[r,n] =       sum_k g_hidden[r,k]     * w2[e][n,k] + b2[e][n]   -> g_ybuf
template <bool LAYER1>
__global__ void __launch_bounds__(256, 2)
gemm_kernel(const float* __restrict__ x,
            const float* __restrict__ W,
            const float* __restrict__ bias) {
    constexpr int K = LAYER1 ? DIM : HIDDEN;
    constexpr int N = LAYER1 ? HIDDEN : DIM;

    int tile = blockIdx.y;
    if (tile >= g_ntiles) return;
    int e     = g_tile_expert[tile];
    int row0  = g_tile_row[tile];
    int mrows = g_tile_m[tile];
    int n0    = blockIdx.x * BN;

    const float* We = W + (size_t)e * N * K;
    const float* be = bias + (size_t)e * N;

    __shared__ float As[BK][BM];
    __shared__ float Bs[BK][BN];

    float c[8][8];
#pragma unroll
    for (int i = 0; i < 8; i++)
#pragma unroll
        for (int j = 0; j < 8; j++) c[i][j] = 0.f;

    int tid = threadIdx.x;
    int ty = tid >> 4, tx = tid & 15;

    for (int k0 = 0; k0 < K; k0 += BK) {
        // load A tile (128 x 16), transposed into As[k][m]
#pragma unroll
        for (int p = 0; p < 2; p++) {
            int idx = tid + p * 256;     // 0..511
            int m = idx >> 2, kv = idx & 3;
            float4 v = make_float4(0.f, 0.f, 0.f, 0.f);
            if (m < mrows) {
                const float* arow;
                if (LAYER1)
                    arow = x + (size_t)g_row_token[row0 + m] * K;
                else
                    arow = g_hidden + (size_t)(row0 + m) * K;
                v = *(const float4*)(arow + k0 + kv * 4);
            }
            As[kv * 4 + 0][m] = v.x;
            As[kv * 4 + 1][m] = v.y;
            As[kv * 4 + 2][m] = v.z;
            As[kv * 4 + 3][m] = v.w;
        }
        // load B tile (128 x 16) from W rows (n-major, k contiguous)
#pragma unroll
        for (int p = 0; p < 2; p++) {
            int idx = tid + p * 256;
            int n = idx >> 2, kv = idx & 3;
            float4 v = *(const float4*)(We + (size_t)(n0 + n) * K + k0 + kv * 4);
            Bs[kv * 4 + 0][n] = v.x;
            Bs[kv * 4 + 1][n] = v.y;
            Bs[kv * 4 + 2][n] = v.z;
            Bs[kv * 4 + 3][n] = v.w;
        }
        __syncthreads();

#pragma unroll
        for (int k = 0; k < BK; k++) {
            float a[8], b[8];
            *(float4*)(a)     = *(const float4*)&As[k][ty * 8];
            *(float4*)(a + 4) = *(const float4*)&As[k][ty * 8 + 4];
            *(float4*)(b)     = *(const float4*)&Bs[k][tx * 8];
            *(float4*)(b + 4) = *(const float4*)&Bs[k][tx * 8 + 4];
#pragma unroll
            for (int i = 0; i < 8; i++)
#pragma unroll
                for (int j = 0; j < 8; j++) c[i][j] += a[i] * b[j];
        }
        __syncthreads();
    }

    // epilogue
#pragma unroll
    for (int i = 0; i < 8; i++) {
        int m = ty * 8 + i;
        if (m >= mrows) continue;
        size_t rbase = (size_t)(row0 + m) * N + n0 + tx * 8;
        float v[8];
#pragma unroll
        for (int j = 0; j < 8; j++) {
            float t = c[i][j] + be[n0 + tx * 8 + j];
            v[j] = LAYER1 ? gelu_exact(t) : t;
        }
        float* out = LAYER1 ? g_hidden : g_ybuf;
        *(float4*)(out + rbase)     = make_float4(v[0], v[1], v[2], v[3]);
        *(float4*)(out + rbase + 4) = make_float4(v[4], v[5], v[6], v[7]);
    }
}

// ---------------- deterministic gated combine ----------------
__global__ void combine_kernel(float* __restrict__ out) {
    int t = blockIdx.x;
    int r0 = g_token_row[t * 2 + 0];
    int r1 = g_token_row[t * 2 + 1];
    float g0 = g_topk_gate[t * 2 + 0];
    float g1 = g_topk_gate[t * 2 + 1];
    const float* y0 = g_ybuf + (size_t)r0 * DIM;
    const float* y1 = g_ybuf + (size_t)r1 * DIM;
    float* o = out + (size_t)t * DIM;
    for (int c = threadIdx.x; c < DIM; c += 256)
        o[c] = g0 * y0[c] + g1 * y1[c];
}

// ---------------- launch ----------------
extern "C" void kernel_launch(void* const* d_in, const int* in_sizes, int n_in,
                              void* d_out, int out_size) {
    const float* x   = (const float*)d_in[0];
    const float* rw  = (const float*)d_in[1];
    const float* w1  = (const float*)d_in[2];
    const float* b1  = (const float*)d_in[3];
    const float* w2  = (const float*)d_in[4];
    const float* b2  = (const float*)d_in[5];
    float* out = (float*)d_out;

    int write_aux = (out_size > T_TOKENS * DIM) ? 1 : 0;

    init_kernel<<<1, 32>>>();
    router_kernel<<<T_TOKENS / 8, 256>>>(x, rw);
    schedule_kernel<<<1, 32>>>(out, write_aux);
    scatter_kernel<<<(T_TOKENS + 255) / 256, 256>>>();
    gemm_kernel<true><<<dim3(HIDDEN / BN, MAXTILES), 256>>>(x, w1, b1);
    gemm_kernel<false><<<dim3(DIM / BN, MAXTILES), 256>>>(x, w2, b2);
    combine_kernel<<<T_TOKENS, 256>>>(out);
}

// round 9
// speedup vs baseline: 2.1815x; 2.1815x over previous
#include <cuda_runtime.h>
#include <cuda_bf16.h>
#include <math.h>
#include <stdint.h>

#define T_TOKENS   8192
#define DIM        1024
#define HIDDEN     2048
#define NEXP       8
#define TOPK       2
#define NROWS      (T_TOKENS * TOPK)   // 16384

#define BM 128
#define BN 128
#define BK 32                      // bf16 k-elements per stage
#define ROWB 80                    // padded row stride (64B data + 16B pad)
#define TILE_SZ (BM * ROWB)        // 10240 B per operand tile
#define STAGE   (4 * TILE_SZ)      // Ahi, Alo, Bhi, Blo
#define SMEM_DYN (2 * STAGE)       // 81920 B
#define MAXTILES 136

// ---------------- scratch ----------------
__device__ uint32_t g_hidden2[(size_t)NROWS * HIDDEN]; // packed bf16 hi | lo<<16
__device__ float    g_ybuf[(size_t)NROWS * DIM];
__device__ int   g_counts[NEXP];
__device__ int   g_cursor[NEXP];
__device__ int   g_offsets[NEXP];
__device__ float g_psum[NEXP];
__device__ int   g_topk_idx[T_TOKENS * TOPK];
__device__ float g_topk_gate[T_TOKENS * TOPK];
__device__ int   g_row_token[NROWS];
__device__ int   g_token_row[T_TOKENS * TOPK];
__device__ int   g_tile_expert[MAXTILES];
__device__ int   g_tile_row[MAXTILES];
__device__ int   g_tile_m[MAXTILES];
__device__ int   g_ntiles;

// ---------------- helpers ----------------
__device__ __forceinline__ uint32_t s2u(const void* p) {
    uint32_t a;
    asm("{ .reg .u64 t; cvta.to.shared.u64 t, %1; cvt.u32.u64 %0, t; }" : "=r"(a) : "l"(p));
    return a;
}

#define LDSM4(r, addr) \
    asm volatile("ldmatrix.sync.aligned.m8n8.x4.shared.b16 {%0,%1,%2,%3}, [%4];" \
        : "=r"((r)[0]), "=r"((r)[1]), "=r"((r)[2]), "=r"((r)[3]) : "r"(addr) : "memory")

#define MMA16816(d, a, b0, b1) \
    asm volatile("mma.sync.aligned.m16n8k16.row.col.f32.bf16.bf16.f32 " \
        "{%0,%1,%2,%3}, {%4,%5,%6,%7}, {%8,%9}, {%0,%1,%2,%3};" \
        : "+f"((d)[0]), "+f"((d)[1]), "+f"((d)[2]), "+f"((d)[3]) \
        : "r"((a)[0]), "r"((a)[1]), "r"((a)[2]), "r"((a)[3]), "r"(b0), "r"(b1))

// split 8 fp32 -> bf16 hi (uint4) + bf16 lo residual (uint4); element k-order kept
__device__ __forceinline__ void split8(const uint4& u0, const uint4& u1,
                                       uint4& hi, uint4& lo) {
    float v[8];
    v[0] = __uint_as_float(u0.x); v[1] = __uint_as_float(u0.y);
    v[2] = __uint_as_float(u0.z); v[3] = __uint_as_float(u0.w);
    v[4] = __uint_as_float(u1.x); v[5] = __uint_as_float(u1.y);
    v[6] = __uint_as_float(u1.z); v[7] = __uint_as_float(u1.w);
    uint32_t h[4], l[4];
#pragma unroll
    for (int p = 0; p < 4; p++) {
        float a = v[2*p], b = v[2*p+1];
        uint32_t hp;
        asm("cvt.rn.bf16x2.f32 %0, %1, %2;" : "=r"(hp) : "f"(b), "f"(a)); // lo=a, hi=b
        float ra = a - __uint_as_float(hp << 16);
        float rb = b - __uint_as_float(hp & 0xffff0000u);
        uint32_t lp;
        asm("cvt.rn.bf16x2.f32 %0, %1, %2;" : "=r"(lp) : "f"(rb), "f"(ra));
        h[p] = hp; l[p] = lp;
    }
    hi = make_uint4(h[0], h[1], h[2], h[3]);
    lo = make_uint4(l[0], l[1], l[2], l[3]);
}

__device__ __forceinline__ float gelu_exact(float v) {
    return 0.5f * v * (1.f + erff(v * 0.70710678118654752f));
}

// ---------------- small kernels (unchanged, verified passing) ----------------
__global__ void init_kernel() {
    int i = threadIdx.x;
    if (i < NEXP) { g_counts[i] = 0; g_cursor[i] = 0; g_psum[i] = 0.f; }
}

__global__ void router_kernel(const float* __restrict__ x,
                              const float* __restrict__ rw) {
    __shared__ float s_rw[NEXP * DIM];
    for (int i = threadIdx.x; i < NEXP * DIM; i += 256) s_rw[i] = rw[i];
    __syncthreads();
    int warp = threadIdx.x >> 5, lane = threadIdx.x & 31;
    int t = blockIdx.x * 8 + warp;
    const float* xr = x + (size_t)t * DIM;
    float acc[NEXP];
#pragma unroll
    for (int e = 0; e < NEXP; e++) acc[e] = 0.f;
    for (int j = lane; j < DIM; j += 32) {
        float xv = xr[j];
#pragma unroll
        for (int e = 0; e < NEXP; e++) acc[e] += xv * s_rw[e * DIM + j];
    }
#pragma unroll
    for (int e = 0; e < NEXP; e++)
#pragma unroll
        for (int o = 16; o > 0; o >>= 1)
            acc[e] += __shfl_down_sync(0xffffffff, acc[e], o);
    if (lane == 0) {
        float m = acc[0];
#pragma unroll
        for (int e = 1; e < NEXP; e++) m = fmaxf(m, acc[e]);
        float p[NEXP], s = 0.f;
#pragma unroll
        for (int e = 0; e < NEXP; e++) { p[e] = expf(acc[e] - m); s += p[e]; }
        float inv = 1.f / s;
#pragma unroll
        for (int e = 0; e < NEXP; e++) atomicAdd(&g_psum[e], p[e] * inv);
        int i1 = 0;
#pragma unroll
        for (int e = 1; e < NEXP; e++) if (acc[e] > acc[i1]) i1 = e;
        int i2 = (i1 == 0) ? 1 : 0;
#pragma unroll
        for (int e = 0; e < NEXP; e++)
            if (e != i1 && acc[e] > acc[i2]) i2 = e;
        float g1 = 1.f / (1.f + expf(acc[i2] - acc[i1]));
        float g2 = 1.f - g1;
        g_topk_idx[t*2+0] = i1;  g_topk_idx[t*2+1] = i2;
        g_topk_gate[t*2+0] = g1; g_topk_gate[t*2+1] = g2;
        atomicAdd(&g_counts[i1], 1);
        atomicAdd(&g_counts[i2], 1);
    }
}

__global__ void schedule_kernel(float* __restrict__ d_out, int write_aux) {
    if (threadIdx.x == 0) {
        int off = 0, nt = 0;
        for (int e = 0; e < NEXP; e++) {
            g_offsets[e] = off;
            int n = g_counts[e];
            for (int rs = 0; rs < n; rs += BM) {
                g_tile_expert[nt] = e;
                g_tile_row[nt]    = off + rs;
                g_tile_m[nt]      = min(BM, n - rs);
                nt++;
            }
            off += n;
        }
        g_ntiles = nt;
        if (write_aux) {
            float aux = 0.f;
            for (int e = 0; e < NEXP; e++)
                aux += ((float)g_counts[e] / (float)NROWS) * (g_psum[e] / (float)T_TOKENS);
            d_out[(size_t)T_TOKENS * DIM] = (float)NEXP * aux;
        }
    }
}

__global__ void scatter_kernel() {
    int t = blockIdx.x * 256 + threadIdx.x;
    if (t >= T_TOKENS) return;
#pragma unroll
    for (int k = 0; k < TOPK; k++) {
        int e   = g_topk_idx[t*2+k];
        int pos = atomicAdd(&g_cursor[e], 1);
        int r   = g_offsets[e] + pos;
        g_row_token[r]     = t;
        g_token_row[t*2+k] = r;
    }
}

// ---------------- grouped GEMM on mma.sync bf16 (split x3, fp32 accum) ----------------
// L1:  hidden = gelu(x_gathered @ w1^T + b1)  -> g_hidden2 (packed bf16 hi/lo)
// !L1: y      = hidden @ w2^T + b2            -> g_ybuf (fp32)
template <int KTOT, int NTOT, bool L1>
__global__ void __launch_bounds__(256, 1)
gemm_mma(const float* __restrict__ xsrc, const float* __restrict__ W,
         const float* __restrict__ bias) {
    int tile = blockIdx.y;
    if (tile >= g_ntiles) return;
    int e     = g_tile_expert[tile];
    int row0  = g_tile_row[tile];
    int mrows = g_tile_m[tile];
    int n0    = blockIdx.x * BN;

    extern __shared__ char sm[];
    uint32_t sb = s2u(sm);

    int tid = threadIdx.x, lane = tid & 31, wid = tid >> 5;
    int wm = (wid & 1) * 64;        // warp m-origin within CTA tile
    int wn = (wid >> 1) * 32;       // warp n-origin

    const float* We = W + ((size_t)e * NTOT + n0) * KTOT;
    const float* be = bias + (size_t)e * NTOT + n0;

    // ---- per-thread load items: 2 A items + 2 B items, each 8 elements (32B) ----
    const uint32_t* aBase[2];
    const uint32_t* bBase[2];
    bool aOk[2];
    int ra[2], ca[2];
#pragma unroll
    for (int t = 0; t < 2; t++) {
        int idx = tid + 256 * t;       // 0..511
        int r = idx >> 2, c = idx & 3; // row, 16B chunk (8 elems)
        ra[t] = r; ca[t] = c;
        aOk[t] = (r < mrows);
        if (L1) {
            int tok = aOk[t] ? g_row_token[row0 + r] : 0;
            aBase[t] = (const uint32_t*)xsrc + (size_t)tok * KTOT + c * 8;
        } else {
            int rr = aOk[t] ? (row0 + r) : 0;
            aBase[t] = g_hidden2 + (size_t)rr * KTOT + c * 8;
        }
        bBase[t] = (const uint32_t*)We + (size_t)r * KTOT + c * 8;
    }

    uint4 sA[2][2], sB[2][2];   // staged gmem data (raw words)
    float acc[4][4][4];
#pragma unroll
    for (int i = 0; i < 4; i++)
#pragma unroll
        for (int j = 0; j < 4; j++)
#pragma unroll
            for (int q = 0; q < 4; q++) acc[i][j][q] = 0.f;

    auto load_regs = [&](int kc) {
        int k0 = kc * BK;
#pragma unroll
        for (int t = 0; t < 2; t++) {
            if (aOk[t]) {
                sA[t][0] = *(const uint4*)(aBase[t] + k0);
                sA[t][1] = *(const uint4*)(aBase[t] + k0 + 4);
            } else {
                sA[t][0] = make_uint4(0, 0, 0, 0);
                sA[t][1] = make_uint4(0, 0, 0, 0);
            }
            sB[t][0] = *(const uint4*)(bBase[t] + k0);
            sB[t][1] = *(const uint4*)(bBase[t] + k0 + 4);
        }
    };

    auto store_smem = [&](int s) {
        char* base = sm + s * STAGE;
#pragma unroll
        for (int t = 0; t < 2; t++) {
            int off = ra[t] * ROWB + ca[t] * 16;
            uint4 hi, lo;
            if (L1) {
                split8(sA[t][0], sA[t][1], hi, lo);
            } else {
                uint4 u0 = sA[t][0], u1 = sA[t][1];
                hi.x = __byte_perm(u0.x, u0.y, 0x5410);
                hi.y = __byte_perm(u0.z, u0.w, 0x5410);
                hi.z = __byte_perm(u1.x, u1.y, 0x5410);
                hi.w = __byte_perm(u1.z, u1.w, 0x5410);
                lo.x = __byte_perm(u0.x, u0.y, 0x7632);
                lo.y = __byte_perm(u0.z, u0.w, 0x7632);
                lo.z = __byte_perm(u1.x, u1.y, 0x7632);
                lo.w = __byte_perm(u1.z, u1.w, 0x7632);
            }
            *(uint4*)(base + off)           = hi;
            *(uint4*)(base + TILE_SZ + off) = lo;
            split8(sB[t][0], sB[t][1], hi, lo);
            *(uint4*)(base + 2 * TILE_SZ + off) = hi;
            *(uint4*)(base + 3 * TILE_SZ + off) = lo;
        }
    };

    auto compute = [&](int s) {
        uint32_t Ab = sb + s * STAGE;
#pragma unroll
        for (int h = 0; h < 2; h++) {          // two k16 halves of BK=32
            int cb = 2 * h + (lane >> 4);      // 16B chunk index
            int rA = wm + (lane & 15);
            uint32_t ah[4][4], al[4][4];
#pragma unroll
            for (int i = 0; i < 4; i++) {
                uint32_t ad = Ab + (uint32_t)((rA + i * 16) * ROWB + cb * 16);
                LDSM4(ah[i], ad);
                LDSM4(al[i], ad + TILE_SZ);
            }
            int rB = wn + (lane & 15);
            uint32_t bh[2][4], bl[2][4];
#pragma unroll
            for (int j = 0; j < 2; j++) {
                uint32_t bd = Ab + 2 * TILE_SZ +
                              (uint32_t)((rB + j * 16) * ROWB + cb * 16);
                LDSM4(bh[j], bd);
                LDSM4(bl[j], bd + TILE_SZ);
            }
#pragma unroll
            for (int i = 0; i < 4; i++)
#pragma unroll
                for (int j = 0; j < 4; j++) {
                    int jj = j >> 1, ss = j & 1;
                    MMA16816(acc[i][j], ah[i], bh[jj][ss], bh[jj][ss + 2]);
                    MMA16816(acc[i][j], ah[i], bl[jj][ss], bl[jj][ss + 2]);
                    MMA16816(acc[i][j], al[i], bh[jj][ss], bh[jj][ss + 2]);
                }
        }
    };

    constexpr int NC = KTOT / BK;
    load_regs(0);
    store_smem(0);
    __syncthreads();
    load_regs(1);
    for (int c = 0; c < NC; c++) {
        compute(c & 1);
        if (c + 1 < NC) {
            store_smem((c + 1) & 1);
            __syncthreads();
            if (c + 2 < NC) load_regs(c + 2);
        }
    }

    // ---- epilogue: bias (+gelu/pack for L1), direct register -> gmem ----
#pragma unroll
    for (int j = 0; j < 4; j++) {
        int colw = wn + j * 8 + 2 * (lane & 3);
        float b0 = __ldg(be + colw);
        float b1 = __ldg(be + colw + 1);
#pragma unroll
        for (int i = 0; i < 4; i++) {
#pragma unroll
            for (int rh = 0; rh < 2; rh++) {
                int m = wm + i * 16 + (lane >> 2) + rh * 8;
                if (m >= mrows) continue;
                float v0 = acc[i][j][rh * 2 + 0] + b0;
                float v1 = acc[i][j][rh * 2 + 1] + b1;
                size_t gbase = (size_t)(row0 + m) * NTOT + n0 + colw;
                if (L1) {
                    v0 = gelu_exact(v0);
                    v1 = gelu_exact(v1);
                    uint32_t h0 = (uint32_t)__bfloat16_as_ushort(__float2bfloat16(v0));
                    float r0f = v0 - __uint_as_float(h0 << 16);
                    uint32_t l0 = (uint32_t)__bfloat16_as_ushort(__float2bfloat16(r0f));
                    uint32_t h1 = (uint32_t)__bfloat16_as_ushort(__float2bfloat16(v1));
                    float r1f = v1 - __uint_as_float(h1 << 16);
                    uint32_t l1 = (uint32_t)__bfloat16_as_ushort(__float2bfloat16(r1f));
                    uint2 w = make_uint2(h0 | (l0 << 16), h1 | (l1 << 16));
                    *(uint2*)(g_hidden2 + gbase) = w;
                } else {
                    *(float2*)(g_ybuf + gbase) = make_float2(v0, v1);
                }
            }
        }
    }
}

// ---------------- deterministic gated combine ----------------
__global__ void combine_kernel(float* __restrict__ out) {
    int t = blockIdx.x;
    int r0 = g_token_row[t*2+0], r1 = g_token_row[t*2+1];
    float g0 = g_topk_gate[t*2+0], g1 = g_topk_gate[t*2+1];
    const float* y0 = g_ybuf + (size_t)r0 * DIM;
    const float* y1 = g_ybuf + (size_t)r1 * DIM;
    float* o = out + (size_t)t * DIM;
    for (int c = threadIdx.x; c < DIM; c += 256)
        o[c] = g0 * y0[c] + g1 * y1[c];
}

// ---------------- launch ----------------
extern "C" void kernel_launch(void* const* d_in, const int* in_sizes, int n_in,
                              void* d_out, int out_size) {
    const float* x  = (const float*)d_in[0];
    const float* rw = (const float*)d_in[1];
    const float* w1 = (const float*)d_in[2];
    const float* b1 = (const float*)d_in[3];
    const float* w2 = (const float*)d_in[4];
    const float* b2 = (const float*)d_in[5];
    float* out = (float*)d_out;

    int write_aux = (out_size > T_TOKENS * DIM) ? 1 : 0;

    static int attr_done = 0;
    if (!attr_done) {
        cudaFuncSetAttribute(gemm_mma<DIM, HIDDEN, true>,
                             cudaFuncAttributeMaxDynamicSharedMemorySize, SMEM_DYN);
        cudaFuncSetAttribute(gemm_mma<HIDDEN, DIM, false>,
                             cudaFuncAttributeMaxDynamicSharedMemorySize, SMEM_DYN);
        attr_done = 1;
    }

    init_kernel<<<1, 32>>>();
    router_kernel<<<T_TOKENS / 8, 256>>>(x, rw);
    schedule_kernel<<<1, 32>>>(out, write_aux);
    scatter_kernel<<<(T_TOKENS + 255) / 256, 256>>>();
    gemm_mma<DIM, HIDDEN, true><<<dim3(HIDDEN / BN, MAXTILES), 256, SMEM_DYN>>>(x, w1, b1);
    gemm_mma<HIDDEN, DIM, false><<<dim3(DIM / BN, MAXTILES), 256, SMEM_DYN>>>(nullptr, w2, b2);
    combine_kernel<<<T_TOKENS, 256>>>(out);
}